// round 11
// baseline (speedup 1.0000x reference)
#include <cuda_runtime.h>
#include <cstdint>

#define THETA 0.7f

// SMEM (float indices):
//  OFF_B4 = 0:     current half's weights [9 tap][64 oc][32 cin tf32, XOR-swizzled] = 18432 floats
//  OFF_S4 = 18432: s buffer [3 sr][132 slot][32 cin tf32, XOR-swizzled]             = 12672 floats
//  (epilogue stages D into the weight region: 64 oc x pitch 132 = 8448 floats)
#define OFF_B4 0
#define OFF_S4 18432
#define SMEM_TOTAL 124416

// W' tf32-rounded, swizzled: [half][tap][oc][cin32 ^ ((oc&7)<<2)]
__device__ float g_Wprep[2 * 9 * 64 * 32];

__device__ __forceinline__ int refl(int i, int n) {
    if (i < 0) i = -i;
    if (i >= n) i = 2 * n - 2 - i;
    return i;
}
__device__ __forceinline__ uint32_t tf32r(float v) {
    uint32_t t;
    asm("cvt.rna.tf32.f32 %0, %1;" : "=r"(t) : "f"(v));
    return t;
}
__device__ __forceinline__ void mma1688(float* d, uint32_t a0, uint32_t a1, uint32_t a2,
                                        uint32_t a3, uint32_t b0, uint32_t b1) {
    asm volatile(
        "mma.sync.aligned.m16n8k8.row.col.f32.tf32.tf32.f32 "
        "{%0,%1,%2,%3},{%4,%5,%6,%7},{%8,%9},{%0,%1,%2,%3};"
        : "+f"(d[0]), "+f"(d[1]), "+f"(d[2]), "+f"(d[3])
        : "r"(a0), "r"(a1), "r"(a2), "r"(a3), "r"(b0), "r"(b1));
}

// W'[oc][cin][tap], center tap -= THETA*sum(taps); tf32-rounded, swizzled.
__global__ void prep_w_kernel(const float* __restrict__ W) {
    int idx = blockIdx.x * blockDim.x + threadIdx.x;
    if (idx >= 64 * 64 * 9) return;
    int oc = idx / 576, rem = idx % 576, cin = rem / 9, tap = rem % 9;
    const float* base = W + oc * 576 + cin * 9;
    float v = base[tap];
    if (tap == 4) {
        float s = 0.f;
#pragma unroll
        for (int t = 0; t < 9; t++) s += base[t];
        v -= THETA * s;
    }
    int dst = (((cin >> 5) * 9 + tap) * 64 + oc) * 32 + ((cin & 31) ^ ((oc & 7) << 2));
    g_Wprep[dst] = __uint_as_float(tf32r(v));
}

// One block per (output row y0, batch b). 256 threads, 8 warps.
// GEMM: M=128 px, N=64 oc, K=576. Warp tile 32M x 32N (R7 shape, regs ~151).
__global__ __launch_bounds__(256, 1)
void conv_mma_kernel(const float* __restrict__ x, float* __restrict__ out) {
    extern __shared__ float sf[];
    uint32_t* us = (uint32_t*)sf;
    const int tid = threadIdx.x, wid = tid >> 5, lane = tid & 31;
    const int warpM = wid & 3, warpN = wid >> 2;
    const int gr = lane >> 2, gc = lane & 3;      // A-frag lanes
    const int kb = lane & 3, ocq = lane >> 2;     // B-frag lanes
    const int y0 = blockIdx.x, b = blockIdx.y;

    float d[2][4][4];
#pragma unroll
    for (int i = 0; i < 2; i++)
#pragma unroll
        for (int j = 0; j < 4; j++)
#pragma unroll
            for (int r = 0; r < 4; r++) d[i][j][r] = 0.f;

    int xrg[5];
#pragma unroll
    for (int i = 0; i < 5; i++) xrg[i] = refl(y0 - 2 + i, 128);

    // Zero-pad slots 0 and 129 of each of the 3 s rows (never written by build).
    if (tid < 192) {
        const int sr = tid >> 6, slot = ((tid >> 5) & 1) * 129, cl = tid & 31;
        sf[OFF_S4 + (sr * 132 + slot) * 32 + cl] = 0.f;
    }

    for (int half = 0; half < 2; half++) {
        __syncthreads();   // previous half's smem fully consumed

        // Load this half's weights (73728B, float4 coalesced).
        {
            const float4* wsrc = (const float4*)(g_Wprep + half * 18432);
            float4* wdst = (float4*)sf;
            for (int i = tid; i < 4608; i += 256) wdst[i] = wsrc[i];
        }

        // Build s = box3x3(reflect-pad x), zero rows outside image, tf32.
        // Warp wid owns cin-group wid (4 cin); lane = column; 4 chunks of 32 cols.
        // Horizontal 3-sum via shuffles from ONE coalesced load per row.
#pragma unroll
        for (int chunk = 0; chunk < 4; chunk++) {
            const int c = chunk * 32 + lane;
            float h[4][5];
#pragma unroll
            for (int i = 0; i < 4; i++) {
                const float* xp = x + (((size_t)b * 64 + half * 32 + wid * 4 + i) << 14);
#pragma unroll
                for (int xr = 0; xr < 5; xr++) {
                    const float* rp = xp + xrg[xr] * 128;
                    float v = rp[c];
                    float rn = __shfl_down_sync(0xFFFFFFFFu, v, 1);
                    float ln = __shfl_up_sync(0xFFFFFFFFu, v, 1);
                    if (lane == 0)  ln = (chunk == 0) ? rn : rp[c - 1];   // refl(-1)=1
                    if (lane == 31) rn = (chunk == 3) ? ln : rp[c + 1];   // refl(128)=126
                    h[i][xr] = ln + v + rn;
                }
            }
#pragma unroll
            for (int sr = 0; sr < 3; sr++) {
                const int vsy = y0 - 1 + sr;
                const bool vr = (vsy >= 0) && (vsy < 128);
                float4 v4;
                v4.x = __uint_as_float(tf32r(vr ? h[0][sr] + h[0][sr + 1] + h[0][sr + 2] : 0.f));
                v4.y = __uint_as_float(tf32r(vr ? h[1][sr] + h[1][sr + 1] + h[1][sr + 2] : 0.f));
                v4.z = __uint_as_float(tf32r(vr ? h[2][sr] + h[2][sr + 1] + h[2][sr + 2] : 0.f));
                v4.w = __uint_as_float(tf32r(vr ? h[3][sr] + h[3][sr + 1] + h[3][sr + 2] : 0.f));
                const int R = sr * 132 + c + 1;
                *(float4*)(sf + OFF_S4 + R * 32 + ((wid << 2) ^ ((R & 7) << 2))) = v4;
            }
        }
        __syncthreads();

        // MMA mainloop: 9 taps x 4 k-groups. Tap (dy,dx) = row/slot offset into s.
        for (int dy = 0; dy < 3; dy++) {
#pragma unroll
            for (int dx = 0; dx < 3; dx++) {
                const int Rb = dy * 132 + dx + warpM * 32 + gr;    // + mt*16, +8 in-frag
                const int xa = ((4 * dy + dx + gr) & 7) << 2;      // swizzle key (R&7)<<2
                const int abase = OFF_S4 + Rb * 32;
                const int bbase = OFF_B4 + ((dy * 3 + dx) * 64 + warpN * 32 + ocq) * 32;
#pragma unroll
                for (int j = 0; j < 4; j++) {
                    const int ca0 = (j * 8 + gc) ^ xa;
                    const int ca1 = (j * 8 + gc + 4) ^ xa;
                    const int cb0 = (j * 8 + kb) ^ (ocq << 2);
                    const int cb1 = (j * 8 + kb + 4) ^ (ocq << 2);
                    uint32_t a[2][4];
#pragma unroll
                    for (int mt = 0; mt < 2; mt++) {
                        const int ab = abase + mt * (16 * 32);
                        a[mt][0] = us[ab + ca0];
                        a[mt][1] = us[ab + 8 * 32 + ca0];
                        a[mt][2] = us[ab + ca1];
                        a[mt][3] = us[ab + 8 * 32 + ca1];
                    }
#pragma unroll
                    for (int nt = 0; nt < 4; nt++) {
                        const uint32_t b0 = us[bbase + nt * 256 + cb0];
                        const uint32_t b1 = us[bbase + nt * 256 + cb1];
#pragma unroll
                        for (int mt = 0; mt < 2; mt++)
                            mma1688(d[mt][nt], a[mt][0], a[mt][1], a[mt][2], a[mt][3], b0, b1);
                    }
                }
            }
        }
    }

    // Epilogue: stage D[oc][p] in weight region (pitch 132, conflict-free), coalesced STG.
    __syncthreads();
#pragma unroll
    for (int mt = 0; mt < 2; mt++)
#pragma unroll
        for (int nt = 0; nt < 4; nt++)
#pragma unroll
            for (int r = 0; r < 4; r++) {
                const int p = warpM * 32 + mt * 16 + gr + 8 * (r >> 1);
                const int oc = warpN * 32 + nt * 8 + 2 * kb + (r & 1);
                sf[oc * 132 + p] = d[mt][nt][r];
            }
    __syncthreads();
#pragma unroll
    for (int it = 0; it < 32; it++) {
        const int idx = it * 256 + tid;
        const int oc = idx >> 7, p = idx & 127;
        out[(((size_t)b * 64 + oc) << 14) + (size_t)y0 * 128 + p] = sf[oc * 132 + p];
    }
}

extern "C" void kernel_launch(void* const* d_in, const int* in_sizes, int n_in,
                              void* d_out, int out_size) {
    const float* x = (const float*)d_in[0];   // [16,64,128,128]
    const float* W = (const float*)d_in[1];   // [64,64,3,3]
    float* out = (float*)d_out;               // [16,64,128,128]

    prep_w_kernel<<<(64 * 64 * 9 + 255) / 256, 256>>>(W);

    cudaFuncSetAttribute(conv_mma_kernel, cudaFuncAttributeMaxDynamicSharedMemorySize,
                         SMEM_TOTAL);
    dim3 grid(128, 16);
    conv_mma_kernel<<<grid, 256, SMEM_TOTAL>>>(x, out);
}

// round 12
// speedup vs baseline: 3.5992x; 3.5992x over previous
#include <cuda_runtime.h>
#include <cstdint>

#define THETA 0.7f

// SMEM (float indices):
//  OFF_B4 = 0:     current half's weights [9 tap][64 oc][32 cin tf32, XOR-swizzled] = 18432 floats
//  OFF_S4 = 18432: s buffer [3 sr][132 slot][32 cin tf32, XOR-swizzled]             = 12672 floats
//  (epilogue stages D into the weight region: 64 oc x pitch 132 = 8448 floats)
#define OFF_B4 0
#define OFF_S4 18432
#define SMEM_TOTAL 124416

// W' tf32-rounded, swizzled: [half][tap][oc][cin32 ^ ((oc&7)<<2)]
__device__ float g_Wprep[2 * 9 * 64 * 32];

__device__ __forceinline__ int refl(int i, int n) {
    if (i < 0) i = -i;
    if (i >= n) i = 2 * n - 2 - i;
    return i;
}
__device__ __forceinline__ uint32_t tf32r(float v) {
    uint32_t t;
    asm("cvt.rna.tf32.f32 %0, %1;" : "=r"(t) : "f"(v));
    return t;
}
__device__ __forceinline__ void mma1688(float* d, uint32_t a0, uint32_t a1, uint32_t a2,
                                        uint32_t a3, uint32_t b0, uint32_t b1) {
    asm volatile(
        "mma.sync.aligned.m16n8k8.row.col.f32.tf32.tf32.f32 "
        "{%0,%1,%2,%3},{%4,%5,%6,%7},{%8,%9},{%0,%1,%2,%3};"
        : "+f"(d[0]), "+f"(d[1]), "+f"(d[2]), "+f"(d[3])
        : "r"(a0), "r"(a1), "r"(a2), "r"(a3), "r"(b0), "r"(b1));
}

// W'[oc][cin][tap], center tap -= THETA*sum(taps); tf32-rounded, swizzled.
__global__ void prep_w_kernel(const float* __restrict__ W) {
    int idx = blockIdx.x * blockDim.x + threadIdx.x;
    if (idx >= 64 * 64 * 9) return;
    int oc = idx / 576, rem = idx % 576, cin = rem / 9, tap = rem % 9;
    const float* base = W + oc * 576 + cin * 9;
    float v = base[tap];
    if (tap == 4) {
        float s = 0.f;
#pragma unroll
        for (int t = 0; t < 9; t++) s += base[t];
        v -= THETA * s;
    }
    int dst = (((cin >> 5) * 9 + tap) * 64 + oc) * 32 + ((cin & 31) ^ ((oc & 7) << 2));
    g_Wprep[dst] = __uint_as_float(tf32r(v));
}

// One block per (output row y0, batch b). 256 threads, 8 warps.
// GEMM: M=128 px, N=64 oc, K=576. Warp tile 32M x 32N (R7 shape).
// Build is R7's branch-free 3-LDG version; s stored ONCE (dx = slot offset).
__global__ __launch_bounds__(256, 1)
void conv_mma_kernel(const float* __restrict__ x, float* __restrict__ out) {
    extern __shared__ float sf[];
    uint32_t* us = (uint32_t*)sf;
    const int tid = threadIdx.x, wid = tid >> 5, lane = tid & 31;
    const int warpM = wid & 3, warpN = wid >> 2;
    const int gr = lane >> 2, gc = lane & 3;      // A-frag lanes
    const int kb = lane & 3, ocq = lane >> 2;     // B-frag lanes
    const int y0 = blockIdx.x, b = blockIdx.y;

    float d[2][4][4];
#pragma unroll
    for (int i = 0; i < 2; i++)
#pragma unroll
        for (int j = 0; j < 4; j++)
#pragma unroll
            for (int r = 0; r < 4; r++) d[i][j][r] = 0.f;

    int xrg[5];
#pragma unroll
    for (int i = 0; i < 5; i++) xrg[i] = refl(y0 - 2 + i, 128);

    // Zero-pad slots 0 and 129 of each of the 3 s rows (never written by build).
    if (tid < 192) {
        const int sr = tid >> 6, slot = ((tid >> 5) & 1) * 129, cl = tid & 31;
        sf[OFF_S4 + (sr * 132 + slot) * 32 + cl] = 0.f;
    }

    for (int half = 0; half < 2; half++) {
        __syncthreads();   // previous half's smem fully consumed

        // Load this half's weights (73728B, float4 coalesced).
        {
            const float4* wsrc = (const float4*)(g_Wprep + half * 18432);
            float4* wdst = (float4*)sf;
            for (int i = tid; i < 4608; i += 256) wdst[i] = wsrc[i];
        }

        // Build s = box3x3(reflect-pad x), zero rows outside image, tf32.
        // R7's branch-free 3-LDG horizontal sum; ONE store per (u, sr).
        for (int u = wid; u < 32; u += 8) {
            const int cg = u & 7, chunk = u >> 3;
            const int c = chunk * 32 + lane;
            const int cm = c ? c - 1 : 1;
            const int cp = (c == 127) ? 126 : c + 1;
            float acc[4][3];
#pragma unroll
            for (int i = 0; i < 4; i++)
#pragma unroll
                for (int sr = 0; sr < 3; sr++) acc[i][sr] = 0.f;
#pragma unroll
            for (int i = 0; i < 4; i++) {
                const float* xp = x + (((size_t)b * 64 + half * 32 + cg * 4 + i) << 14);
#pragma unroll
                for (int xr = 0; xr < 5; xr++) {
                    const float* rp = xp + xrg[xr] * 128;
                    float h = rp[cm] + rp[c] + rp[cp];
                    if (xr < 3)            acc[i][xr]     += h;
                    if (xr >= 1 && xr < 4) acc[i][xr - 1] += h;
                    if (xr >= 2)           acc[i][xr - 2] += h;
                }
            }
#pragma unroll
            for (int sr = 0; sr < 3; sr++) {
                const int vsy = y0 - 1 + sr;
                const bool vr = (vsy >= 0) && (vsy < 128);
                float4 v4;
                v4.x = __uint_as_float(tf32r(vr ? acc[0][sr] : 0.f));
                v4.y = __uint_as_float(tf32r(vr ? acc[1][sr] : 0.f));
                v4.z = __uint_as_float(tf32r(vr ? acc[2][sr] : 0.f));
                v4.w = __uint_as_float(tf32r(vr ? acc[3][sr] : 0.f));
                const int R = sr * 132 + c + 1;
                *(float4*)(sf + OFF_S4 + R * 32 + ((cg << 2) ^ ((R & 7) << 2))) = v4;
            }
        }
        __syncthreads();

        // MMA mainloop: 9 taps x 4 k-groups. Tap (dy,dx) = row/slot offset into s.
        for (int dy = 0; dy < 3; dy++) {
#pragma unroll
            for (int dx = 0; dx < 3; dx++) {
                const int Rb = dy * 132 + dx + warpM * 32 + gr;    // + mt*16, +8 in-frag
                const int xa = ((4 * dy + dx + gr) & 7) << 2;      // swizzle key (R&7)<<2
                const int abase = OFF_S4 + Rb * 32;
                const int bbase = OFF_B4 + ((dy * 3 + dx) * 64 + warpN * 32 + ocq) * 32;
#pragma unroll
                for (int j = 0; j < 4; j++) {
                    const int ca0 = (j * 8 + gc) ^ xa;
                    const int ca1 = (j * 8 + gc + 4) ^ xa;
                    const int cb0 = (j * 8 + kb) ^ (ocq << 2);
                    const int cb1 = (j * 8 + kb + 4) ^ (ocq << 2);
                    uint32_t a[2][4];
#pragma unroll
                    for (int mt = 0; mt < 2; mt++) {
                        const int ab = abase + mt * (16 * 32);
                        a[mt][0] = us[ab + ca0];
                        a[mt][1] = us[ab + 8 * 32 + ca0];
                        a[mt][2] = us[ab + ca1];
                        a[mt][3] = us[ab + 8 * 32 + ca1];
                    }
#pragma unroll
                    for (int nt = 0; nt < 4; nt++) {
                        const uint32_t b0 = us[bbase + nt * 256 + cb0];
                        const uint32_t b1 = us[bbase + nt * 256 + cb1];
#pragma unroll
                        for (int mt = 0; mt < 2; mt++)
                            mma1688(d[mt][nt], a[mt][0], a[mt][1], a[mt][2], a[mt][3], b0, b1);
                    }
                }
            }
        }
    }

    // Epilogue: stage D[oc][p] in weight region (pitch 132, conflict-free), coalesced STG.
    __syncthreads();
#pragma unroll
    for (int mt = 0; mt < 2; mt++)
#pragma unroll
        for (int nt = 0; nt < 4; nt++)
#pragma unroll
            for (int r = 0; r < 4; r++) {
                const int p = warpM * 32 + mt * 16 + gr + 8 * (r >> 1);
                const int oc = warpN * 32 + nt * 8 + 2 * kb + (r & 1);
                sf[oc * 132 + p] = d[mt][nt][r];
            }
    __syncthreads();
#pragma unroll
    for (int it = 0; it < 32; it++) {
        const int idx = it * 256 + tid;
        const int oc = idx >> 7, p = idx & 127;
        out[(((size_t)b * 64 + oc) << 14) + (size_t)y0 * 128 + p] = sf[oc * 132 + p];
    }
}

extern "C" void kernel_launch(void* const* d_in, const int* in_sizes, int n_in,
                              void* d_out, int out_size) {
    const float* x = (const float*)d_in[0];   // [16,64,128,128]
    const float* W = (const float*)d_in[1];   // [64,64,3,3]
    float* out = (float*)d_out;               // [16,64,128,128]

    prep_w_kernel<<<(64 * 64 * 9 + 255) / 256, 256>>>(W);

    cudaFuncSetAttribute(conv_mma_kernel, cudaFuncAttributeMaxDynamicSharedMemorySize,
                         SMEM_TOTAL);
    dim3 grid(128, 16);
    conv_mma_kernel<<<grid, 256, SMEM_TOTAL>>>(x, out);
}

// round 14
// speedup vs baseline: 4.1339x; 1.1485x over previous
#include <cuda_runtime.h>
#include <cstdint>

#define THETA 0.7f

// SMEM (float indices): single region, 12672 floats = 50688 B.
//  OFF_S4 = 0: s buffer [3 sr][132 slot][32 cin tf32, XOR-swizzled]
//  (epilogue stages D here afterward: 64 oc x pitch 132 = 8448 floats)
#define OFF_S4 0
#define SMEM_TOTAL 50688

// B fragments pre-baked for direct per-thread LDG.64:
// idx = ((((half*9+tap)*2 + warpN)*4 + nt)*4 + j)*32 + (kb*8 + ocq)
// value = { W'[oc][k], W'[oc][k+4] },  oc = warpN*32+nt*8+ocq,  k = half*32+j*8+kb
__device__ float2 g_Wldg[2 * 9 * 2 * 4 * 4 * 32];

__device__ __forceinline__ int refl(int i, int n) {
    if (i < 0) i = -i;
    if (i >= n) i = 2 * n - 2 - i;
    return i;
}
__device__ __forceinline__ uint32_t tf32r(float v) {
    uint32_t t;
    asm("cvt.rna.tf32.f32 %0, %1;" : "=r"(t) : "f"(v));
    return t;
}
__device__ __forceinline__ void mma1688(float* d, uint32_t a0, uint32_t a1, uint32_t a2,
                                        uint32_t a3, uint32_t b0, uint32_t b1) {
    asm volatile(
        "mma.sync.aligned.m16n8k8.row.col.f32.tf32.tf32.f32 "
        "{%0,%1,%2,%3},{%4,%5,%6,%7},{%8,%9},{%0,%1,%2,%3};"
        : "+f"(d[0]), "+f"(d[1]), "+f"(d[2]), "+f"(d[3])
        : "r"(a0), "r"(a1), "r"(a2), "r"(a3), "r"(b0), "r"(b1));
}

// Effective weight W'[oc][cin][tap] = W - (tap==4)*THETA*sum(taps), tf32-rounded.
__device__ __forceinline__ float wprime(const float* W, int oc, int cin, int tap) {
    const float* base = W + oc * 576 + cin * 9;
    float v = base[tap];
    if (tap == 4) {
        float s = 0.f;
#pragma unroll
        for (int t = 0; t < 9; t++) s += base[t];
        v -= THETA * s;
    }
    return __uint_as_float(tf32r(v));
}

__global__ void prep_w_kernel(const float* __restrict__ W) {
    int idx = blockIdx.x * blockDim.x + threadIdx.x;
    if (idx >= 2 * 9 * 2 * 4 * 4 * 32) return;
    int t = idx;
    const int o  = t & 31; t >>= 5;
    const int j  = t & 3;  t >>= 2;
    const int nt = t & 3;  t >>= 2;
    const int wN = t & 1;  t >>= 1;
    const int tap = t % 9;
    const int half = t / 9;
    const int oc = wN * 32 + nt * 8 + (o & 7);
    const int k0 = half * 32 + j * 8 + (o >> 3);
    g_Wldg[idx] = make_float2(wprime(W, oc, k0, tap), wprime(W, oc, k0 + 4, tap));
}

// One block per (output row y0, batch b). 256 threads, 8 warps, 2 blocks/SM.
// GEMM: M=128 px, N=64 oc, K=576. Warp tile 32M x 32N. A from SMEM, B via LDG.
__global__ __launch_bounds__(256, 2)
void conv_mma_kernel(const float* __restrict__ x, float* __restrict__ out) {
    extern __shared__ float sf[];
    uint32_t* us = (uint32_t*)sf;
    const int tid = threadIdx.x, wid = tid >> 5, lane = tid & 31;
    const int warpM = wid & 3, warpN = wid >> 2;
    const int gr = lane >> 2, gc = lane & 3;      // A-frag lanes
    const int kb = lane & 3, ocq = lane >> 2;     // B-frag lanes
    const int y0 = blockIdx.x, b = blockIdx.y;

    float d[2][4][4];
#pragma unroll
    for (int i = 0; i < 2; i++)
#pragma unroll
        for (int j = 0; j < 4; j++)
#pragma unroll
            for (int r = 0; r < 4; r++) d[i][j][r] = 0.f;

    int xrg[5];
#pragma unroll
    for (int i = 0; i < 5; i++) xrg[i] = refl(y0 - 2 + i, 128);

    // Zero-pad slots 0 and 129 of each of the 3 s rows (never written by build).
    if (tid < 192) {
        const int sr = tid >> 6, slot = ((tid >> 5) & 1) * 129, cl = tid & 31;
        sf[OFF_S4 + (sr * 132 + slot) * 32 + cl] = 0.f;
    }

    // Per-thread B pointer base (lane part is constant).
    const float2* wbase = g_Wldg + (size_t)(kb * 8 + ocq);

    for (int half = 0; half < 2; half++) {
        __syncthreads();   // previous half's s fully consumed

        // Build s = box3x3(reflect-pad x), zero rows outside image, tf32.
        // Branch-free 3-LDG horizontal sum; ONE float4 store per (u, sr).
        for (int u = wid; u < 32; u += 8) {
            const int cg = u & 7, chunk = u >> 3;
            const int c = chunk * 32 + lane;
            const int cm = c ? c - 1 : 1;
            const int cp = (c == 127) ? 126 : c + 1;
            float acc[4][3];
#pragma unroll
            for (int i = 0; i < 4; i++)
#pragma unroll
                for (int sr = 0; sr < 3; sr++) acc[i][sr] = 0.f;
#pragma unroll
            for (int i = 0; i < 4; i++) {
                const float* xp = x + (((size_t)b * 64 + half * 32 + cg * 4 + i) << 14);
#pragma unroll
                for (int xr = 0; xr < 5; xr++) {
                    const float* rp = xp + xrg[xr] * 128;
                    float h = rp[cm] + rp[c] + rp[cp];
                    if (xr < 3)            acc[i][xr]     += h;
                    if (xr >= 1 && xr < 4) acc[i][xr - 1] += h;
                    if (xr >= 2)           acc[i][xr - 2] += h;
                }
            }
#pragma unroll
            for (int sr = 0; sr < 3; sr++) {
                const int vsy = y0 - 1 + sr;
                const bool vr = (vsy >= 0) && (vsy < 128);
                float4 v4;
                v4.x = __uint_as_float(tf32r(vr ? acc[0][sr] : 0.f));
                v4.y = __uint_as_float(tf32r(vr ? acc[1][sr] : 0.f));
                v4.z = __uint_as_float(tf32r(vr ? acc[2][sr] : 0.f));
                v4.w = __uint_as_float(tf32r(vr ? acc[3][sr] : 0.f));
                const int R = sr * 132 + c + 1;
                *(float4*)(sf + OFF_S4 + R * 32 + ((cg << 2) ^ ((R & 7) << 2))) = v4;
            }
        }
        __syncthreads();

        // MMA mainloop: 9 taps x 4 k-groups. A from SMEM; B via per-thread LDG.64.
        for (int dy = 0; dy < 3; dy++) {
#pragma unroll
            for (int dx = 0; dx < 3; dx++) {
                const int tap = dy * 3 + dx;
                const int Rb = dy * 132 + dx + warpM * 32 + gr;
                const int xa = ((4 * dy + dx + gr) & 7) << 2;      // swizzle key (R&7)<<2
                const int abase = OFF_S4 + Rb * 32;
                const float2* wtap = wbase + (size_t)(((half * 9 + tap) * 2 + warpN)) * 512;
#pragma unroll
                for (int j = 0; j < 4; j++) {
                    const int ca0 = (j * 8 + gc) ^ xa;
                    const int ca1 = (j * 8 + gc + 4) ^ xa;
                    float2 bv[4];
#pragma unroll
                    for (int nt = 0; nt < 4; nt++)
                        bv[nt] = __ldg(wtap + (nt * 4 + j) * 32);
                    uint32_t a[2][4];
#pragma unroll
                    for (int mt = 0; mt < 2; mt++) {
                        const int ab = abase + mt * (16 * 32);
                        a[mt][0] = us[ab + ca0];
                        a[mt][1] = us[ab + 8 * 32 + ca0];
                        a[mt][2] = us[ab + ca1];
                        a[mt][3] = us[ab + 8 * 32 + ca1];
                    }
#pragma unroll
                    for (int nt = 0; nt < 4; nt++) {
                        const uint32_t b0 = __float_as_uint(bv[nt].x);
                        const uint32_t b1 = __float_as_uint(bv[nt].y);
#pragma unroll
                        for (int mt = 0; mt < 2; mt++)
                            mma1688(d[mt][nt], a[mt][0], a[mt][1], a[mt][2], a[mt][3], b0, b1);
                    }
                }
            }
        }
    }

    // Epilogue: stage D[oc][p] in the s region (pitch 132, conflict-free), coalesced STG.
    __syncthreads();
#pragma unroll
    for (int mt = 0; mt < 2; mt++)
#pragma unroll
        for (int nt = 0; nt < 4; nt++)
#pragma unroll
            for (int r = 0; r < 4; r++) {
                const int p = warpM * 32 + mt * 16 + gr + 8 * (r >> 1);
                const int oc = warpN * 32 + nt * 8 + 2 * kb + (r & 1);
                sf[oc * 132 + p] = d[mt][nt][r];
            }
    __syncthreads();
#pragma unroll
    for (int it = 0; it < 32; it++) {
        const int idx = it * 256 + tid;
        const int oc = idx >> 7, p = idx & 127;
        out[(((size_t)b * 64 + oc) << 14) + (size_t)y0 * 128 + p] = sf[oc * 132 + p];
    }
}

extern "C" void kernel_launch(void* const* d_in, const int* in_sizes, int n_in,
                              void* d_out, int out_size) {
    const float* x = (const float*)d_in[0];   // [16,64,128,128]
    const float* W = (const float*)d_in[1];   // [64,64,3,3]
    float* out = (float*)d_out;               // [16,64,128,128]

    prep_w_kernel<<<(2 * 9 * 2 * 4 * 4 * 32 + 255) / 256, 256>>>(W);

    cudaFuncSetAttribute(conv_mma_kernel, cudaFuncAttributeMaxDynamicSharedMemorySize,
                         SMEM_TOTAL);
    dim3 grid(128, 16);
    conv_mma_kernel<<<grid, 256, SMEM_TOTAL>>>(x, out);
}